// round 14
// baseline (speedup 1.0000x reference)
#include <cuda_runtime.h>
#include <cuda_bf16.h>
#include <cstdint>

// ---------------------------------------------------------------------------
// LRU forward on GB300, round 14: mega-kernel with PER-TILE release flags
// (fine-grained cross-block pipeline: scan(b,c) waits only tiles j<=c).
//   blocks [0,512):    gemm1 tile (b,lt)  -> BuF, uG, ends; release flag1[tile]
//   blocks [512,1024): scan tile (b,lt)   -> preG (+states); acquire flag1 j<=c
//   blocks [1024,1536):gemm2 tile (b,lt)  -> y; acquire flag2[tile]
// ---------------------------------------------------------------------------

#define BB   8
#define LL   8192
#define HH   128
#define NN   256
#define OO   128
#define TCH  128
#define NCH  (LL / TCH)   // 64
#define NT   (BB * NCH)   // 512 tiles

#define O_A4 0
#define O_B4 (128 * 32)
#define SMEM_U4 (128 * 32 + 64 * 32)     // 6144 uint4
#define SMEM_B  (SMEM_U4 * 16)           // 98304 bytes

// ------------------------- scratch (static device) -------------------------
__device__ float    g_BuF[(size_t)BB * LL * 512];    // 134 MB, (re,im) interleaved
__device__ float2   g_lam[NN];
__device__ float2   g_lamP[NCH * NN];                // lamT^k
__device__ float2   g_end[BB * NCH * NN];
__device__ uint4    g_preG[(size_t)NT * 4 * 4096];   // 128 MB pre-state granules
__device__ uint4    g_uG[(size_t)NT * 4096];         // 32 MB u granules
__device__ uint4    g_B14[512 * 32];
__device__ uint4    g_B24[5 * 128 * 32];
__device__ int      g_flag1[NT];                     // gemm1 tile completion
__device__ int      g_flag2[NT];                     // scan tile completion

// ------------------------------ helpers -------------------------------------
__device__ __forceinline__ int gslot(int row, int gq) {
    return row * 32 + (gq ^ ((row & 1) << 2));
}

__device__ __forceinline__ void split_pair(float v0, float v1,
                                           uint32_t& hi, uint32_t& lo) {
    __nv_bfloat16 h0 = __float2bfloat16(v0);
    __nv_bfloat16 h1 = __float2bfloat16(v1);
    __nv_bfloat16 l0 = __float2bfloat16(v0 - __bfloat162float(h0));
    __nv_bfloat16 l1 = __float2bfloat16(v1 - __bfloat162float(h1));
    hi = (uint32_t)__bfloat16_as_ushort(h0) | ((uint32_t)__bfloat16_as_ushort(h1) << 16);
    lo = (uint32_t)__bfloat16_as_ushort(l0) | ((uint32_t)__bfloat16_as_ushort(l1) << 16);
}

__device__ __forceinline__ void mma16816(float* d,
                                         uint32_t a0, uint32_t a1, uint32_t a2, uint32_t a3,
                                         uint32_t b0, uint32_t b1) {
    asm volatile("mma.sync.aligned.m16n8k16.row.col.f32.bf16.bf16.f32 "
                 "{%0,%1,%2,%3},{%4,%5,%6,%7},{%8,%9},{%0,%1,%2,%3};"
                 : "+f"(d[0]), "+f"(d[1]), "+f"(d[2]), "+f"(d[3])
                 : "r"(a0), "r"(a1), "r"(a2), "r"(a3), "r"(b0), "r"(b1));
}

__device__ __forceinline__ void cp_async16(uint4* smem_dst, const uint4* gsrc) {
    uint32_t s = (uint32_t)__cvta_generic_to_shared(smem_dst);
    asm volatile("cp.async.cg.shared.global [%0], [%1], 16;" :: "r"(s), "l"(gsrc));
}
#define CP_COMMIT() asm volatile("cp.async.commit_group;" ::: "memory")
#define CP_WAIT0()  asm volatile("cp.async.wait_group 0;" ::: "memory")

// ------------------------------- prep ---------------------------------------
__global__ void prep_kernel(const float* __restrict__ nu_log,
                            const float* __restrict__ theta_log,
                            const float* __restrict__ gamma_log,
                            const float* __restrict__ Bp_re,
                            const float* __restrict__ Bp_im,
                            const float* __restrict__ C_re,
                            const float* __restrict__ C_im,
                            const float* __restrict__ D) {
    int idx = blockIdx.x * blockDim.x + threadIdx.x;   // 0..49151

    if (idx < NT) { g_flag1[idx] = 0; g_flag2[idx] = 0; }

    if (idx < NN) {
        float nu = expf(nu_log[idx]);
        float a  = expf(-nu);
        float th = expf(theta_log[idx]);
        g_lam[idx] = make_float2(a * cosf(th), a * sinf(th));
    }
    if (idx < NCH * NN) {   // lamT^k (double-precision powers)
        int k = idx >> 8;
        int n = idx & (NN - 1);
        double nu = exp((double)nu_log[n]);
        double th = exp((double)theta_log[n]);
        double r   = exp(-nu * (double)TCH * (double)k);
        double ang = th * (double)TCH * (double)k;
        g_lamP[idx] = make_float2((float)(r * cos(ang)), (float)(r * sin(ang)));
    }
    // B1 granules: 512 rows (r = 2n+im) x 32 granules
    if (idx < 512 * 32) {
        int r  = idx >> 5;
        int gq = idx & 31;
        int K = gq >> 2, tq = gq & 3;
        int n  = r >> 1;
        int im = r & 1;
        float gs = expf(gamma_log[n]);
        const float* src = im ? Bp_im : Bp_re;
        int c0 = 2 * (8 * K + tq);
        int c1 = c0 + 8;
        uint32_t h0, l0, h1, l1;
        split_pair(gs * src[n * HH + c0], gs * src[n * HH + c0 + 1], h0, l0);
        split_pair(gs * src[n * HH + c1], gs * src[n * HH + c1 + 1], h1, l1);
        g_B14[(r >> 6) * 64 * 32 + gslot(r & 63, gq)] = make_uint4(h0, h1, l0, l1);
    }
    // B2 granules: 5 k-chunks x 128 rows (o) x 32 granules
    if (idx < 5 * 128 * 32) {
        int c  = idx >> 12;
        int o  = (idx >> 5) & 127;
        int gq = idx & 31;
        int K = gq >> 2, tq = gq & 3;
        int p0 = 8 * K + tq;
        int p1 = p0 + 4;
        float a0, a1, b0, b1;
        if (c < 4) {
            a0 =  C_re[o * NN + c * 64 + p0];
            a1 = -C_im[o * NN + c * 64 + p0];
            b0 =  C_re[o * NN + c * 64 + p1];
            b1 = -C_im[o * NN + c * 64 + p1];
        } else {
            a0 = D[o * HH + 2 * p0];
            a1 = D[o * HH + 2 * p0 + 1];
            b0 = D[o * HH + 2 * p1];
            b1 = D[o * HH + 2 * p1 + 1];
        }
        uint32_t h0, l0, h1, l1;
        split_pair(a0, a1, h0, l0);
        split_pair(b0, b1, h1, l1);
        g_B24[c * 128 * 32 + gslot(o, gq)] = make_uint4(h0, h1, l0, l1);
    }
}

// ------------------------------ role bodies ----------------------------------
__device__ void gemm1_body(const float* __restrict__ u, int b, int lt,
                           uint4* sm4, int tid) {
    uint4* A4 = sm4 + O_A4;
    uint4* B4 = sm4 + O_B4;
    const int wid  = tid >> 5;
    const int lane = tid & 31;
    const int g    = lane >> 2;
    const int tq   = lane & 3;
    const int sgx  = (g & 1) << 2;
    const int l0   = lt * 128;
    const int wr   = (wid & 3) * 32;
    const int wc   = (wid >> 2) * 32;
    const size_t tile = (size_t)b * NCH + lt;

    // pack A tile: U[128 l x 128 h] -> granules
    {
        const float* ut = u + ((size_t)b * LL + l0) * HH;
        #pragma unroll
        for (int i = 0; i < 16; ++i) {
            int p  = tid + 256 * i;
            int row = p >> 5, gq = p & 31;
            int K = gq >> 2, tql = gq & 3;
            int c0 = 2 * (8 * K + tql);
            float2 va = *(const float2*)(ut + row * HH + c0);
            float2 vb = *(const float2*)(ut + row * HH + c0 + 8);
            uint32_t h0, lo0, h1, lo1;
            split_pair(va.x, va.y, h0, lo0);
            split_pair(vb.x, vb.y, h1, lo1);
            A4[gslot(row, gq)] = make_uint4(h0, h1, lo0, lo1);
        }
    }
    __syncthreads();

    // dump packed U granules for gemm2 (kc == 4 chunk)
    {
        uint4* dst = g_uG + tile * 4096;
        #pragma unroll
        for (int i = 0; i < 16; ++i) dst[tid + 256 * i] = A4[tid + 256 * i];
    }

    for (int cc = 0; cc < 8; ++cc) {
        {
            const uint4* gb = g_B14 + cc * 64 * 32;
            #pragma unroll
            for (int i = 0; i < 8; ++i)
                cp_async16(&B4[tid + 256 * i], &gb[tid + 256 * i]);
            CP_COMMIT();
            CP_WAIT0();
        }
        __syncthreads();

        float acc[2][4][4];
        #pragma unroll
        for (int mf = 0; mf < 2; ++mf)
            #pragma unroll
            for (int nf = 0; nf < 4; ++nf)
                #pragma unroll
                for (int q = 0; q < 4; ++q) acc[mf][nf][q] = 0.f;

        #pragma unroll 1
        for (int K = 0; K < 8; ++K) {
            const int kq = (K * 4 + tq) ^ sgx;
            uint32_t ah[2][4], al[2][4];
            #pragma unroll
            for (int mf = 0; mf < 2; ++mf) {
                int r = wr + mf * 16 + g;
                uint4 qa = A4[r * 32 + kq];
                uint4 qb = A4[(r + 8) * 32 + kq];
                ah[mf][0] = qa.x; ah[mf][1] = qb.x; ah[mf][2] = qa.y; ah[mf][3] = qb.y;
                al[mf][0] = qa.z; al[mf][1] = qb.z; al[mf][2] = qa.w; al[mf][3] = qb.w;
            }
            #pragma unroll
            for (int nf = 0; nf < 4; ++nf) {
                int cr = wc + nf * 8 + g;
                uint4 qb = B4[cr * 32 + kq];
                #pragma unroll
                for (int mf = 0; mf < 2; ++mf) {
                    mma16816(acc[mf][nf], ah[mf][0], ah[mf][1], ah[mf][2], ah[mf][3], qb.x, qb.y);
                    mma16816(acc[mf][nf], ah[mf][0], ah[mf][1], ah[mf][2], ah[mf][3], qb.z, qb.w);
                    mma16816(acc[mf][nf], al[mf][0], al[mf][1], al[mf][2], al[mf][3], qb.x, qb.y);
                }
            }
        }

        {
            float* dst = g_BuF + ((size_t)b * LL + l0) * 512 + cc * 64;
            #pragma unroll
            for (int mf = 0; mf < 2; ++mf) {
                int row = wr + mf * 16 + g;
                #pragma unroll
                for (int nf = 0; nf < 4; ++nf) {
                    int col = wc + nf * 8 + 2 * tq;
                    *(float2*)&dst[(size_t)row * 512 + col] =
                        make_float2(acc[mf][nf][0], acc[mf][nf][1]);
                    *(float2*)&dst[(size_t)(row + 8) * 512 + col] =
                        make_float2(acc[mf][nf][2], acc[mf][nf][3]);
                }
            }
        }
        __syncthreads();
    }

    // fused chunk-end scan: re-read own tile (L2-hot), reduce to g_end
    {
        const int n = tid;
        const float2 lam = g_lam[n];
        const float2* bu = (const float2*)g_BuF + ((size_t)b * LL + l0) * NN + n;
        float2 x = make_float2(0.f, 0.f);
        #pragma unroll 1
        for (int j0 = 0; j0 < TCH; j0 += 8) {
            float2 v[8];
            #pragma unroll
            for (int j = 0; j < 8; ++j) v[j] = bu[(size_t)(j0 + j) * NN];
            #pragma unroll
            for (int j = 0; j < 8; ++j) {
                float nr = fmaf(lam.x, x.x, fmaf(-lam.y, x.y, v[j].x));
                float ni = fmaf(lam.x, x.y, fmaf( lam.y, x.x, v[j].y));
                x = make_float2(nr, ni);
            }
        }
        g_end[((size_t)b * NCH + lt) * NN + n] = x;
    }

    // release: all tile data (BuF, uG, ends) visible, then set tile flag
    __threadfence();
    __syncthreads();
    if (tid == 0) atomicExch(&g_flag1[tile], 1);
}

__device__ void scan_body(float2* __restrict__ stc, float* __restrict__ str,
                          int writeG, int b, int c, uint4* sm4, int tid) {
    float2 (*sbuf)[NN] = (float2 (*)[NN])sm4;   // 16 KB overlay

    // acquire: gemm1 tiles (b, 0..c) done — fine-grained prefix wait
    if (tid == 0) {
        for (int j = 0; j <= c; ++j) {
            while (atomicAdd(&g_flag1[b * NCH + j], 0) == 0) __nanosleep(100);
        }
    }
    __syncthreads();
    __threadfence();

    const int n = tid;
    const float2 lam = g_lam[n];
    const size_t tile = (size_t)b * NCH + c;

    float2 x = make_float2(0.f, 0.f);
    for (int j = 0; j < c; ++j) {
        float2 e = g_end[((size_t)b * NCH + j) * NN + n];
        float2 p = g_lamP[(c - 1 - j) * NN + n];
        x.x = fmaf(p.x, e.x, fmaf(-p.y, e.y, x.x));
        x.y = fmaf(p.x, e.y, fmaf( p.y, e.x, x.y));
    }

    const int l0 = c * TCH;
    const float2* bu = (const float2*)g_BuF + ((size_t)b * LL + l0) * NN + n;
    float2* po = stc ? stc + ((size_t)b * (LL + 1) + l0) * NN + n : nullptr;
    float*  so = str ? str + ((size_t)b * (LL + 1) + l0) * NN + n : nullptr;

    for (int j0 = 0; j0 < TCH; j0 += 8) {
        #pragma unroll
        for (int jj = 0; jj < 8; ++jj) {
            int j = j0 + jj;
            sbuf[jj][n] = x;
            if (po) po[(size_t)j * NN] = x;
            if (so) so[(size_t)j * NN] = x.x;
            float2 v = bu[(size_t)j * NN];
            float nr = fmaf(lam.x, x.x, fmaf(-lam.y, x.y, v.x));
            float ni = fmaf(lam.x, x.y, fmaf( lam.y, x.x, v.y));
            x = make_float2(nr, ni);
        }
        __syncthreads();
        if (writeG) {
            #pragma unroll
            for (int t = 0; t < 4; ++t) {
                int gi = n + 256 * t;
                int row8 = gi >> 7;
                int rem  = gi & 127;
                int kc   = rem >> 5;
                int gq   = rem & 31;
                int p0   = 8 * (gq >> 2) + (gq & 3);
                float2 va = sbuf[row8][kc * 64 + p0];
                float2 vb = sbuf[row8][kc * 64 + p0 + 4];
                uint32_t h0, lo0, h1, lo1;
                split_pair(va.x, va.y, h0, lo0);
                split_pair(vb.x, vb.y, h1, lo1);
                int row = j0 + row8;
                g_preG[(tile * 4 + kc) * 4096 + gslot(row, gq)] =
                    make_uint4(h0, h1, lo0, lo1);
            }
        }
        __syncthreads();
    }
    if (c == NCH - 1) {   // final state t = L
        if (po) po[(size_t)TCH * NN] = x;
        if (so) so[(size_t)TCH * NN] = x.x;
    }

    // release: preG tile visible
    __threadfence();
    __syncthreads();
    if (tid == 0) atomicExch(&g_flag2[tile], 1);
}

__device__ void gemm2_body(float* __restrict__ yout, int b, int lt,
                           uint4* sm4, int tid) {
    uint4* A4 = sm4 + O_A4;
    uint4* B4 = sm4 + O_B4;
    const int wid  = tid >> 5;
    const int lane = tid & 31;
    const int g    = lane >> 2;
    const int tq   = lane & 3;
    const int sgx  = (g & 1) << 2;
    const int l0   = lt * 128;
    const int wr   = (wid & 3) * 32;
    const int wc   = (wid >> 2) * 32;
    const size_t tile = (size_t)b * NCH + lt;

    // acquire: this tile's scan done (implies its gemm1 done too)
    if (tid == 0) {
        while (atomicAdd(&g_flag2[tile], 0) == 0) __nanosleep(100);
    }
    __syncthreads();
    __threadfence();

    float acc[2][2][4][4];
    #pragma unroll
    for (int cc = 0; cc < 2; ++cc)
        #pragma unroll
        for (int mf = 0; mf < 2; ++mf)
            #pragma unroll
            for (int nf = 0; nf < 4; ++nf)
                #pragma unroll
                for (int q = 0; q < 4; ++q) acc[cc][mf][nf][q] = 0.f;

    for (int kc = 0; kc < 5; ++kc) {
        {
            const uint4* ga = (kc < 4) ? g_preG + (tile * 4 + kc) * 4096
                                       : g_uG + tile * 4096;
            #pragma unroll
            for (int i = 0; i < 16; ++i)
                cp_async16(&A4[tid + 256 * i], &ga[tid + 256 * i]);
        }
        for (int cc = 0; cc < 2; ++cc) {
            {
                const uint4* gb = g_B24 + (kc * 128 + cc * 64) * 32;
                #pragma unroll
                for (int i = 0; i < 8; ++i)
                    cp_async16(&B4[tid + 256 * i], &gb[tid + 256 * i]);
                CP_COMMIT();
                CP_WAIT0();
            }
            __syncthreads();

            #pragma unroll 1
            for (int K = 0; K < 8; ++K) {
                const int kq = (K * 4 + tq) ^ sgx;
                uint32_t ah[2][4], al[2][4];
                #pragma unroll
                for (int mf = 0; mf < 2; ++mf) {
                    int r = wr + mf * 16 + g;
                    uint4 qa = A4[r * 32 + kq];
                    uint4 qb = A4[(r + 8) * 32 + kq];
                    ah[mf][0] = qa.x; ah[mf][1] = qb.x; ah[mf][2] = qa.y; ah[mf][3] = qb.y;
                    al[mf][0] = qa.z; al[mf][1] = qb.z; al[mf][2] = qa.w; al[mf][3] = qb.w;
                }
                #pragma unroll
                for (int nf = 0; nf < 4; ++nf) {
                    int cr = wc + nf * 8 + g;
                    uint4 qb = B4[cr * 32 + kq];
                    #pragma unroll
                    for (int mf = 0; mf < 2; ++mf) {
                        mma16816(acc[cc][mf][nf], ah[mf][0], ah[mf][1], ah[mf][2], ah[mf][3], qb.x, qb.y);
                        mma16816(acc[cc][mf][nf], ah[mf][0], ah[mf][1], ah[mf][2], ah[mf][3], qb.z, qb.w);
                        mma16816(acc[cc][mf][nf], al[mf][0], al[mf][1], al[mf][2], al[mf][3], qb.x, qb.y);
                    }
                }
            }
            __syncthreads();
        }
    }

    {
        float* dst = yout + ((size_t)b * LL + l0) * OO;
        #pragma unroll
        for (int cc = 0; cc < 2; ++cc)
            #pragma unroll
            for (int mf = 0; mf < 2; ++mf) {
                int row = wr + mf * 16 + g;
                #pragma unroll
                for (int nf = 0; nf < 4; ++nf) {
                    int col = cc * 64 + wc + nf * 8 + 2 * tq;
                    *(float2*)&dst[(size_t)row * OO + col] =
                        make_float2(acc[cc][mf][nf][0], acc[cc][mf][nf][1]);
                    *(float2*)&dst[(size_t)(row + 8) * OO + col] =
                        make_float2(acc[cc][mf][nf][2], acc[cc][mf][nf][3]);
                }
            }
    }
}

// ------------------------------ mega kernel ----------------------------------
__global__ __launch_bounds__(256, 2) void mega_kernel(const float* __restrict__ u,
                                                      float* __restrict__ yout,
                                                      float2* __restrict__ stc,
                                                      float* __restrict__ str) {
    extern __shared__ uint4 sm4[];
    const int role = blockIdx.x >> 9;       // 0: gemm1, 1: scan, 2: gemm2
    const int r    = blockIdx.x & 511;
    const int b    = r >> 6;                // batch-major ordering
    const int lt   = r & 63;
    const int tid  = threadIdx.x;

    if (role == 0) {
        gemm1_body(u, b, lt, sm4, tid);
    } else if (role == 1) {
        scan_body(stc, str, yout != nullptr, b, lt, sm4, tid);
    } else {
        if (yout) gemm2_body(yout, b, lt, sm4, tid);
    }
}

// ------------------------------ launch ---------------------------------------
extern "C" void kernel_launch(void* const* d_in, const int* in_sizes, int n_in,
                              void* d_out, int out_size) {
    const float* u         = (const float*)d_in[0];
    const float* nu_log    = (const float*)d_in[1];
    const float* theta_log = (const float*)d_in[2];
    const float* gamma_log = (const float*)d_in[3];
    const float* Bp_re     = (const float*)d_in[4];
    const float* Bp_im     = (const float*)d_in[5];
    const float* C_re      = (const float*)d_in[6];
    const float* C_im      = (const float*)d_in[7];
    const float* D         = (const float*)d_in[8];

    float* out = (float*)d_out;

    const long long NY  = (long long)BB * LL * OO;
    const long long NSc = (long long)BB * (LL + 1) * NN;
    const long long osz = (long long)out_size;

    float*  yout = nullptr;
    float2* stc  = nullptr;
    float*  str  = nullptr;

    if (osz == NY) {
        yout = out;
    } else if (osz == NY + 2 * NSc) {
        yout = out; stc = (float2*)(out + NY);
    } else if (osz == 2 * NSc) {
        stc = (float2*)out;
    } else if (osz == NSc) {
        stc = (float2*)out;
    } else if (osz == NY + NSc) {
        yout = out; str = out + NY;
    } else {
        yout = out;
    }

    cudaFuncSetAttribute(mega_kernel, cudaFuncAttributeMaxDynamicSharedMemorySize, SMEM_B);

    prep_kernel<<<192, 256>>>(nu_log, theta_log, gamma_log,
                              Bp_re, Bp_im, C_re, C_im, D);
    int nblocks = yout ? 3 * NT : 2 * NT;
    mega_kernel<<<nblocks, 256, SMEM_B>>>(u, yout, stc, str);
}

// round 16
// speedup vs baseline: 1.1057x; 1.1057x over previous
#include <cuda_runtime.h>
#include <cuda_bf16.h>
#include <cstdint>

// ---------------------------------------------------------------------------
// LRU forward on GB300, round 15: round-10 structure (separate kernels), plus
//  - gemm1: B-chunk cp.async hidden under epilogue; uG dumped from registers
//   gemm1: Bu = U @ B1^T  (+ fused per-chunk local scan -> g_end)
//   scan:  carry prologue + final scan -> granules (+ states output if needed)
//   gemm2: y = Pre @ C~^T + U @ D^T   (K = 640, 5 chunks)
// ---------------------------------------------------------------------------

#define BB   8
#define LL   8192
#define HH   128
#define NN   256
#define OO   128
#define TCH  128
#define NCH  (LL / TCH)   // 64
#define NT   (BB * NCH)   // 512 tiles

// smem: A = 128 rows x 32 granules (uint4), B = 64 rows x 32 granules
#define O_A4 0
#define O_B4 (128 * 32)
#define SMEM_U4 (128 * 32 + 64 * 32)     // 6144 uint4
#define SMEM_B  (SMEM_U4 * 16)           // 98304 bytes

// ------------------------- scratch (static device) -------------------------
__device__ float    g_BuF[(size_t)BB * LL * 512];    // 134 MB, (re,im) interleaved
__device__ float2   g_lam[NN];
__device__ float2   g_lamP[NCH * NN];                // lamT^k
__device__ float2   g_end[BB * NCH * NN];
__device__ uint4    g_preG[(size_t)NT * 4 * 4096];   // 128 MB pre-state granules
__device__ uint4    g_uG[(size_t)NT * 4096];         // 32 MB u granules
// pre-packed granule B images
__device__ uint4    g_B14[512 * 32];
__device__ uint4    g_B24[5 * 128 * 32];

// ------------------------------ helpers -------------------------------------
// granule slot with conflict-free swizzle (granule = 16B = 2 k-pairs hi + lo)
__device__ __forceinline__ int gslot(int row, int gq) {
    return row * 32 + (gq ^ ((row & 1) << 2));
}

__device__ __forceinline__ void split_pair(float v0, float v1,
                                           uint32_t& hi, uint32_t& lo) {
    __nv_bfloat16 h0 = __float2bfloat16(v0);
    __nv_bfloat16 h1 = __float2bfloat16(v1);
    __nv_bfloat16 l0 = __float2bfloat16(v0 - __bfloat162float(h0));
    __nv_bfloat16 l1 = __float2bfloat16(v1 - __bfloat162float(h1));
    hi = (uint32_t)__bfloat16_as_ushort(h0) | ((uint32_t)__bfloat16_as_ushort(h1) << 16);
    lo = (uint32_t)__bfloat16_as_ushort(l0) | ((uint32_t)__bfloat16_as_ushort(l1) << 16);
}

__device__ __forceinline__ void mma16816(float* d,
                                         uint32_t a0, uint32_t a1, uint32_t a2, uint32_t a3,
                                         uint32_t b0, uint32_t b1) {
    asm volatile("mma.sync.aligned.m16n8k16.row.col.f32.bf16.bf16.f32 "
                 "{%0,%1,%2,%3},{%4,%5,%6,%7},{%8,%9},{%0,%1,%2,%3};"
                 : "+f"(d[0]), "+f"(d[1]), "+f"(d[2]), "+f"(d[3])
                 : "r"(a0), "r"(a1), "r"(a2), "r"(a3), "r"(b0), "r"(b1));
}

__device__ __forceinline__ void cp_async16(uint4* smem_dst, const uint4* gsrc) {
    uint32_t s = (uint32_t)__cvta_generic_to_shared(smem_dst);
    asm volatile("cp.async.cg.shared.global [%0], [%1], 16;" :: "r"(s), "l"(gsrc));
}
#define CP_COMMIT() asm volatile("cp.async.commit_group;" ::: "memory")
#define CP_WAIT0()  asm volatile("cp.async.wait_group 0;" ::: "memory")

// ------------------------------- prep ---------------------------------------
__global__ void prep_kernel(const float* __restrict__ nu_log,
                            const float* __restrict__ theta_log,
                            const float* __restrict__ gamma_log,
                            const float* __restrict__ Bp_re,
                            const float* __restrict__ Bp_im,
                            const float* __restrict__ C_re,
                            const float* __restrict__ C_im,
                            const float* __restrict__ D) {
    int idx = blockIdx.x * blockDim.x + threadIdx.x;   // 0..49151

    if (idx < NN) {
        float nu = expf(nu_log[idx]);
        float a  = expf(-nu);
        float th = expf(theta_log[idx]);
        g_lam[idx] = make_float2(a * cosf(th), a * sinf(th));
    }
    if (idx < NCH * NN) {   // lamT^k (double-precision powers)
        int k = idx >> 8;
        int n = idx & (NN - 1);
        double nu = exp((double)nu_log[n]);
        double th = exp((double)theta_log[n]);
        double r   = exp(-nu * (double)TCH * (double)k);
        double ang = th * (double)TCH * (double)k;
        g_lamP[idx] = make_float2((float)(r * cos(ang)), (float)(r * sin(ang)));
    }
    // B1 granules: 512 rows (r = 2n+im) x 32 granules
    if (idx < 512 * 32) {
        int r  = idx >> 5;
        int gq = idx & 31;
        int K = gq >> 2, tq = gq & 3;
        int n  = r >> 1;
        int im = r & 1;
        float gs = expf(gamma_log[n]);
        const float* src = im ? Bp_im : Bp_re;
        int c0 = 2 * (8 * K + tq);
        int c1 = c0 + 8;
        uint32_t h0, l0, h1, l1;
        split_pair(gs * src[n * HH + c0], gs * src[n * HH + c0 + 1], h0, l0);
        split_pair(gs * src[n * HH + c1], gs * src[n * HH + c1 + 1], h1, l1);
        g_B14[(r >> 6) * 64 * 32 + gslot(r & 63, gq)] = make_uint4(h0, h1, l0, l1);
    }
    // B2 granules: 5 k-chunks x 128 rows (o) x 32 granules
    if (idx < 5 * 128 * 32) {
        int c  = idx >> 12;
        int o  = (idx >> 5) & 127;
        int gq = idx & 31;
        int K = gq >> 2, tq = gq & 3;
        int p0 = 8 * K + tq;
        int p1 = p0 + 4;
        float a0, a1, b0, b1;
        if (c < 4) {
            a0 =  C_re[o * NN + c * 64 + p0];
            a1 = -C_im[o * NN + c * 64 + p0];
            b0 =  C_re[o * NN + c * 64 + p1];
            b1 = -C_im[o * NN + c * 64 + p1];
        } else {
            a0 = D[o * HH + 2 * p0];
            a1 = D[o * HH + 2 * p0 + 1];
            b0 = D[o * HH + 2 * p1];
            b1 = D[o * HH + 2 * p1 + 1];
        }
        uint32_t h0, l0, h1, l1;
        split_pair(a0, a1, h0, l0);
        split_pair(b0, b1, h1, l1);
        g_B24[c * 128 * 32 + gslot(o, gq)] = make_uint4(h0, h1, l0, l1);
    }
}

// --------- GEMM1: Bu = U @ B1^T  (mma.sync, 3x bf16) + fused chunk-ends ------
__global__ __launch_bounds__(256, 2) void gemm1_kernel(const float* __restrict__ u) {
    extern __shared__ uint4 sm4[];
    uint4* A4 = sm4 + O_A4;
    uint4* B4 = sm4 + O_B4;

    const int lt   = blockIdx.x;          // chunk index == l-tile
    const int b    = blockIdx.y;
    const int tid  = threadIdx.x;
    const int wid  = tid >> 5;
    const int lane = tid & 31;
    const int g    = lane >> 2;
    const int tq   = lane & 3;
    const int sgx  = (g & 1) << 2;
    const int l0   = lt * 128;
    const int wr   = (wid & 3) * 32;
    const int wc   = (wid >> 2) * 32;
    const size_t tile = (size_t)b * NCH + lt;

    // prologue: B chunk 0 in flight under A pack
    {
        const uint4* gb = g_B14;
        #pragma unroll
        for (int i = 0; i < 8; ++i)
            cp_async16(&B4[tid + 256 * i], &gb[tid + 256 * i]);
        CP_COMMIT();
    }

    // pack A tile: U[128 l x 128 h] -> granules; also dump uG from registers
    {
        const float* ut = u + ((size_t)b * LL + l0) * HH;
        uint4* ug = g_uG + tile * 4096;
        #pragma unroll
        for (int i = 0; i < 16; ++i) {
            int p  = tid + 256 * i;            // 4096 granules
            int row = p >> 5, gq = p & 31;
            int K = gq >> 2, tql = gq & 3;
            int c0 = 2 * (8 * K + tql);
            float2 va = *(const float2*)(ut + row * HH + c0);
            float2 vb = *(const float2*)(ut + row * HH + c0 + 8);
            uint32_t h0, lo0, h1, lo1;
            split_pair(va.x, va.y, h0, lo0);
            split_pair(vb.x, vb.y, h1, lo1);
            uint4 v = make_uint4(h0, h1, lo0, lo1);
            int s = gslot(row, gq);
            A4[s] = v;
            ug[s] = v;
        }
    }

    for (int cc = 0; cc < 8; ++cc) {
        CP_WAIT0();
        __syncthreads();   // B(cc) (and A on first iter) visible to all

        float acc[2][4][4];
        #pragma unroll
        for (int mf = 0; mf < 2; ++mf)
            #pragma unroll
            for (int nf = 0; nf < 4; ++nf)
                #pragma unroll
                for (int q = 0; q < 4; ++q) acc[mf][nf][q] = 0.f;

        #pragma unroll 1
        for (int K = 0; K < 8; ++K) {
            const int kq = (K * 4 + tq) ^ sgx;
            uint32_t ah[2][4], al[2][4];
            #pragma unroll
            for (int mf = 0; mf < 2; ++mf) {
                int r = wr + mf * 16 + g;
                uint4 qa = A4[r * 32 + kq];
                uint4 qb = A4[(r + 8) * 32 + kq];
                ah[mf][0] = qa.x; ah[mf][1] = qb.x; ah[mf][2] = qa.y; ah[mf][3] = qb.y;
                al[mf][0] = qa.z; al[mf][1] = qb.z; al[mf][2] = qa.w; al[mf][3] = qb.w;
            }
            #pragma unroll
            for (int nf = 0; nf < 4; ++nf) {
                int cr = wc + nf * 8 + g;
                uint4 qb = B4[cr * 32 + kq];
                #pragma unroll
                for (int mf = 0; mf < 2; ++mf) {
                    mma16816(acc[mf][nf], ah[mf][0], ah[mf][1], ah[mf][2], ah[mf][3], qb.x, qb.y);
                    mma16816(acc[mf][nf], ah[mf][0], ah[mf][1], ah[mf][2], ah[mf][3], qb.z, qb.w);
                    mma16816(acc[mf][nf], al[mf][0], al[mf][1], al[mf][2], al[mf][3], qb.x, qb.y);
                }
            }
        }
        __syncthreads();   // all warps done reading B(cc) -> safe to overwrite

        if (cc < 7) {      // next B copy flies under the epilogue
            const uint4* gb = g_B14 + (cc + 1) * 64 * 32;
            #pragma unroll
            for (int i = 0; i < 8; ++i)
                cp_async16(&B4[tid + 256 * i], &gb[tid + 256 * i]);
            CP_COMMIT();
        }

        // epilogue: (re,im) pairs -> g_BuF (independent of B4)
        {
            float* dst = g_BuF + ((size_t)b * LL + l0) * 512 + cc * 64;
            #pragma unroll
            for (int mf = 0; mf < 2; ++mf) {
                int row = wr + mf * 16 + g;
                #pragma unroll
                for (int nf = 0; nf < 4; ++nf) {
                    int col = wc + nf * 8 + 2 * tq;
                    *(float2*)&dst[(size_t)row * 512 + col] =
                        make_float2(acc[mf][nf][0], acc[mf][nf][1]);
                    *(float2*)&dst[(size_t)(row + 8) * 512 + col] =
                        make_float2(acc[mf][nf][2], acc[mf][nf][3]);
                }
            }
        }
    }

    // ---- fused chunk-end scan: re-read own tile (L2-hot), reduce to g_end ----
    __syncthreads();
    {
        const int n = tid;
        const float2 lam = g_lam[n];
        const float2* bu = (const float2*)g_BuF + ((size_t)b * LL + l0) * NN + n;
        float2 x = make_float2(0.f, 0.f);
        #pragma unroll 1
        for (int j0 = 0; j0 < TCH; j0 += 8) {
            float2 v[8];
            #pragma unroll
            for (int j = 0; j < 8; ++j) v[j] = bu[(size_t)(j0 + j) * NN];
            #pragma unroll
            for (int j = 0; j < 8; ++j) {
                float nr = fmaf(lam.x, x.x, fmaf(-lam.y, x.y, v[j].x));
                float ni = fmaf(lam.x, x.y, fmaf( lam.y, x.x, v[j].y));
                x = make_float2(nr, ni);
            }
        }
        g_end[((size_t)b * NCH + lt) * NN + n] = x;
    }
}

// ------- scan: carry prologue + final scan -> granules (+ states outputs) ----
__global__ __launch_bounds__(256) void scan_kernel(float2* __restrict__ stc,
                                                   float* __restrict__ str,
                                                   int writeG) {
    __shared__ float2 sbuf[8][NN];   // 16 KB staging of pre-states

    const int c = blockIdx.x;
    const int b = blockIdx.y;
    const int n = threadIdx.x;
    const float2 lam = g_lam[n];
    const size_t tile = (size_t)b * NCH + c;

    // carry[c] = sum_{j<c} lamT^(c-1-j) * end[j]
    float2 x = make_float2(0.f, 0.f);
    for (int j = 0; j < c; ++j) {
        float2 e = g_end[((size_t)b * NCH + j) * NN + n];
        float2 p = g_lamP[(c - 1 - j) * NN + n];
        x.x = fmaf(p.x, e.x, fmaf(-p.y, e.y, x.x));
        x.y = fmaf(p.x, e.y, fmaf( p.y, e.x, x.y));
    }

    const int l0 = c * TCH;
    const float2* bu = (const float2*)g_BuF + ((size_t)b * LL + l0) * NN + n;
    float2* po = stc ? stc + ((size_t)b * (LL + 1) + l0) * NN + n : nullptr;
    float*  so = str ? str + ((size_t)b * (LL + 1) + l0) * NN + n : nullptr;

    for (int j0 = 0; j0 < TCH; j0 += 8) {
        #pragma unroll
        for (int jj = 0; jj < 8; ++jj) {
            int j = j0 + jj;
            sbuf[jj][n] = x;
            if (po) po[(size_t)j * NN] = x;
            if (so) so[(size_t)j * NN] = x.x;
            float2 v = bu[(size_t)j * NN];
            float nr = fmaf(lam.x, x.x, fmaf(-lam.y, x.y, v.x));
            float ni = fmaf(lam.x, x.y, fmaf( lam.y, x.x, v.y));
            x = make_float2(nr, ni);
        }
        __syncthreads();
        if (writeG) {
            #pragma unroll
            for (int t = 0; t < 4; ++t) {
                int gi = n + 256 * t;            // 1024 granules per 8-row batch
                int row8 = gi >> 7;
                int rem  = gi & 127;
                int kc   = rem >> 5;
                int gq   = rem & 31;
                int p0   = 8 * (gq >> 2) + (gq & 3);
                float2 va = sbuf[row8][kc * 64 + p0];
                float2 vb = sbuf[row8][kc * 64 + p0 + 4];
                uint32_t h0, lo0, h1, lo1;
                split_pair(va.x, va.y, h0, lo0);
                split_pair(vb.x, vb.y, h1, lo1);
                int row = j0 + row8;
                g_preG[(tile * 4 + kc) * 4096 + gslot(row, gq)] =
                    make_uint4(h0, h1, lo0, lo1);
            }
        }
        __syncthreads();
    }
    if (c == NCH - 1) {   // final state t = L
        if (po) po[(size_t)TCH * NN] = x;
        if (so) so[(size_t)TCH * NN] = x.x;
    }
}

// ------------- GEMM2: y = Pre @ C~^T + U @ D^T  (mma.sync, 3x bf16) ----------
__global__ __launch_bounds__(256, 2) void gemm2_kernel(float* __restrict__ yout) {
    extern __shared__ uint4 sm4[];
    uint4* A4 = sm4 + O_A4;
    uint4* B4 = sm4 + O_B4;

    const int lt   = blockIdx.x;
    const int b    = blockIdx.y;
    const int tid  = threadIdx.x;
    const int wid  = tid >> 5;
    const int lane = tid & 31;
    const int g    = lane >> 2;
    const int tq   = lane & 3;
    const int sgx  = (g & 1) << 2;
    const int l0   = lt * 128;
    const int wr   = (wid & 3) * 32;
    const int wc   = (wid >> 2) * 32;
    const size_t tile = (size_t)b * NCH + lt;

    float acc[2][2][4][4];
    #pragma unroll
    for (int cc = 0; cc < 2; ++cc)
        #pragma unroll
        for (int mf = 0; mf < 2; ++mf)
            #pragma unroll
            for (int nf = 0; nf < 4; ++nf)
                #pragma unroll
                for (int q = 0; q < 4; ++q) acc[cc][mf][nf][q] = 0.f;

    for (int kc = 0; kc < 5; ++kc) {
        // A chunk: identity cp.async from pre-converted granules
        {
            const uint4* ga = (kc < 4) ? g_preG + (tile * 4 + kc) * 4096
                                       : g_uG + tile * 4096;
            #pragma unroll
            for (int i = 0; i < 16; ++i)
                cp_async16(&A4[tid + 256 * i], &ga[tid + 256 * i]);
        }
        for (int cc = 0; cc < 2; ++cc) {
            {
                const uint4* gb = g_B24 + (kc * 128 + cc * 64) * 32;
                #pragma unroll
                for (int i = 0; i < 8; ++i)
                    cp_async16(&B4[tid + 256 * i], &gb[tid + 256 * i]);
                CP_COMMIT();
                CP_WAIT0();
            }
            __syncthreads();

            #pragma unroll 1
            for (int K = 0; K < 8; ++K) {
                const int kq = (K * 4 + tq) ^ sgx;
                uint32_t ah[2][4], al[2][4];
                #pragma unroll
                for (int mf = 0; mf < 2; ++mf) {
                    int r = wr + mf * 16 + g;
                    uint4 qa = A4[r * 32 + kq];
                    uint4 qb = A4[(r + 8) * 32 + kq];
                    ah[mf][0] = qa.x; ah[mf][1] = qb.x; ah[mf][2] = qa.y; ah[mf][3] = qb.y;
                    al[mf][0] = qa.z; al[mf][1] = qb.z; al[mf][2] = qa.w; al[mf][3] = qb.w;
                }
                #pragma unroll
                for (int nf = 0; nf < 4; ++nf) {
                    int cr = wc + nf * 8 + g;
                    uint4 qb = B4[cr * 32 + kq];
                    #pragma unroll
                    for (int mf = 0; mf < 2; ++mf) {
                        mma16816(acc[cc][mf][nf], ah[mf][0], ah[mf][1], ah[mf][2], ah[mf][3], qb.x, qb.y);
                        mma16816(acc[cc][mf][nf], ah[mf][0], ah[mf][1], ah[mf][2], ah[mf][3], qb.z, qb.w);
                        mma16816(acc[cc][mf][nf], al[mf][0], al[mf][1], al[mf][2], al[mf][3], qb.x, qb.y);
                    }
                }
            }
            __syncthreads();
        }
    }

    {
        float* dst = yout + ((size_t)b * LL + l0) * OO;
        #pragma unroll
        for (int cc = 0; cc < 2; ++cc)
            #pragma unroll
            for (int mf = 0; mf < 2; ++mf) {
                int row = wr + mf * 16 + g;
                #pragma unroll
                for (int nf = 0; nf < 4; ++nf) {
                    int col = cc * 64 + wc + nf * 8 + 2 * tq;
                    *(float2*)&dst[(size_t)row * OO + col] =
                        make_float2(acc[cc][mf][nf][0], acc[cc][mf][nf][1]);
                    *(float2*)&dst[(size_t)(row + 8) * OO + col] =
                        make_float2(acc[cc][mf][nf][2], acc[cc][mf][nf][3]);
                }
            }
    }
}

// ------------------------------ launch ---------------------------------------
extern "C" void kernel_launch(void* const* d_in, const int* in_sizes, int n_in,
                              void* d_out, int out_size) {
    const float* u         = (const float*)d_in[0];
    const float* nu_log    = (const float*)d_in[1];
    const float* theta_log = (const float*)d_in[2];
    const float* gamma_log = (const float*)d_in[3];
    const float* Bp_re     = (const float*)d_in[4];
    const float* Bp_im     = (const float*)d_in[5];
    const float* C_re      = (const float*)d_in[6];
    const float* C_im      = (const float*)d_in[7];
    const float* D         = (const float*)d_in[8];

    float* out = (float*)d_out;

    const long long NY  = (long long)BB * LL * OO;
    const long long NSc = (long long)BB * (LL + 1) * NN;
    const long long osz = (long long)out_size;

    float*  yout = nullptr;
    float2* stc  = nullptr;
    float*  str  = nullptr;

    if (osz == NY) {
        yout = out;
    } else if (osz == NY + 2 * NSc) {
        yout = out; stc = (float2*)(out + NY);
    } else if (osz == 2 * NSc) {
        stc = (float2*)out;
    } else if (osz == NSc) {
        stc = (float2*)out;
    } else if (osz == NY + NSc) {
        yout = out; str = out + NY;
    } else {
        yout = out;
    }

    cudaFuncSetAttribute(gemm1_kernel, cudaFuncAttributeMaxDynamicSharedMemorySize, SMEM_B);
    cudaFuncSetAttribute(gemm2_kernel, cudaFuncAttributeMaxDynamicSharedMemorySize, SMEM_B);

    prep_kernel<<<192, 256>>>(nu_log, theta_log, gamma_log,
                              Bp_re, Bp_im, C_re, C_im, D);
    gemm1_kernel<<<dim3(LL / 128, BB), 256, SMEM_B>>>(u);
    scan_kernel<<<dim3(NCH, BB), 256>>>(stc, str, yout ? 1 : 0);
    if (yout)
        gemm2_kernel<<<dim3(LL / 128, BB), 256, SMEM_B>>>(yout);
}